// round 8
// baseline (speedup 1.0000x reference)
#include <cuda_runtime.h>
#include <mma.h>

using namespace nvcuda;

// Problem constants
#define BB 128       // batch
#define TT 256       // timesteps
#define HH 1024      // hidden
#define II 150       // input features (J*D = 50*3)
#define CC 60        // classes
#define KC 64        // K-chunk staged in SMEM
#define KCP 68       // padded row stride (floats): 272B -> 4-bank row shift, kills 8-way conflicts
#define MJ 16        // hidden units per CTA tile
#define NJT (HH/MJ)  // 64 j-tiles per layer

// Dynamic SMEM: As (64 rows) + Bs (128 rows), each KCP floats wide.
#define SM_FLOATS (64 * KCP + 128 * KCP)
#define SM_BYTES  (SM_FLOATS * 4)

// Ping-pong state buffers: [h1 x2, c1 x2, h2 x2, c2 x2], each B*H floats (4 MB total)
__device__ float g_buf[8][BB * HH];

typedef wmma::fragment<wmma::matrix_a, 16, 16, 8, wmma::precision::tf32, wmma::row_major> FragA;
typedef wmma::fragment<wmma::matrix_b, 16, 16, 8, wmma::precision::tf32, wmma::col_major> FragB;
typedef wmma::fragment<wmma::accumulator, 16, 16, 8, float> FragC;

struct Params {
    const float *x;
    const float *Wih1, *Whh1, *bih1, *bhh1;
    const float *Wih2, *Whh2, *bih2, *bhh2;
    const float *h1_in, *c1_in, *h2_in, *c2_in;
    float *h1_out, *c1_out, *h2_out, *c2_out;
    int p;
};

__device__ __forceinline__ float sigm(float v) { return 1.0f / (1.0f + expf(-v)); }

// Accumulates acc += W_tile @ B^T over K, for 4 gates x MJ rows x 128 batch.
// W: [4H, K] row-major, rows used: g*HH + jt*MJ + j  (g in 0..3, j in 0..15)
// Bsrc: rows = batch (128), row stride ldb, K valid columns (zero-padded to KC).
// AL4 = true requires: K % KC == 0, ldb % 4 == 0, 16B-aligned bases (K=1024 paths).
// Software-pipelined: chunk k0's data is prefetched into registers during the
// MMA of chunk k0-KC, so LDG latency overlaps tensor compute.
template<bool AL4>
__device__ void gemm_part(const float* __restrict__ W, int K,
                          const float* __restrict__ Bsrc, long ldb,
                          int jt, float* As, float* Bs, FragC acc[4])
{
    const int tid  = threadIdx.x;
    const int warp = tid >> 5;

    // Register prefetch buffers (only one of the two sets is live per template inst.)
    float4 rA4[4], rB4[8];
    float  rAs[16], rBs[32];

    const int q  = tid & 15;            // AL4: float4 column (0..15)
    const int rs = tid >> 4;            // AL4: staged row offset (0..15)
    const int lr = tid >> 6;            // scalar: row offset (0..3)
    const int kk = tid & 63;            // scalar: column (0..63)

    const float4* W4 = (const float4*)W;
    const float4* B4 = (const float4*)Bsrc;
    const long Kq   = (long)(K >> 2);
    const long ldb4 = ldb >> 2;

    // Prefetch chunk 0
    if (AL4) {
        const long kw4 = q;
        #pragma unroll
        for (int rr = 0; rr < 4; rr++) {
            int r   = rr * 16 + rs;
            int row = (r >> 4) * HH + jt * MJ + (r & 15);
            rA4[rr] = W4[(long)row * Kq + kw4];
        }
        #pragma unroll
        for (int rr = 0; rr < 8; rr++) {
            int r = rr * 16 + rs;
            rB4[rr] = B4[(long)r * ldb4 + kw4];
        }
    } else {
        const int  k  = kk;
        const bool kv = (k < K);
        #pragma unroll
        for (int rr = 0; rr < 16; rr++) {
            int r   = rr * 4 + lr;
            int row = (r >> 4) * HH + jt * MJ + (r & 15);
            rAs[rr] = kv ? W[(long)row * K + k] : 0.0f;
        }
        #pragma unroll
        for (int rr = 0; rr < 32; rr++) {
            int r = rr * 4 + lr;
            rBs[rr] = kv ? Bsrc[(long)r * ldb + k] : 0.0f;
        }
    }

    for (int k0 = 0; k0 < K; k0 += KC) {
        __syncthreads();                 // previous chunk's MMA done reading SMEM
        // Commit prefetched registers -> SMEM
        if (AL4) {
            float4* As4 = (float4*)As;
            float4* Bs4 = (float4*)Bs;
            #pragma unroll
            for (int rr = 0; rr < 4; rr++) {
                int r = rr * 16 + rs;
                As4[r * (KCP / 4) + q] = rA4[rr];
            }
            #pragma unroll
            for (int rr = 0; rr < 8; rr++) {
                int r = rr * 16 + rs;
                Bs4[r * (KCP / 4) + q] = rB4[rr];
            }
        } else {
            #pragma unroll
            for (int rr = 0; rr < 16; rr++) {
                int r = rr * 4 + lr;
                As[r * KCP + kk] = rAs[rr];
            }
            #pragma unroll
            for (int rr = 0; rr < 32; rr++) {
                int r = rr * 4 + lr;
                Bs[r * KCP + kk] = rBs[rr];
            }
        }
        __syncthreads();                 // chunk visible to all warps

        // Prefetch NEXT chunk into registers — overlaps the MMA below
        const int kn = k0 + KC;
        if (kn < K) {
            if (AL4) {
                const long kw4 = (long)(kn >> 2) + q;
                #pragma unroll
                for (int rr = 0; rr < 4; rr++) {
                    int r   = rr * 16 + rs;
                    int row = (r >> 4) * HH + jt * MJ + (r & 15);
                    rA4[rr] = W4[(long)row * Kq + kw4];
                }
                #pragma unroll
                for (int rr = 0; rr < 8; rr++) {
                    int r = rr * 16 + rs;
                    rB4[rr] = B4[(long)r * ldb4 + kw4];
                }
            } else {
                const int  k  = kn + kk;
                const bool kv = (k < K);
                #pragma unroll
                for (int rr = 0; rr < 16; rr++) {
                    int r   = rr * 4 + lr;
                    int row = (r >> 4) * HH + jt * MJ + (r & 15);
                    rAs[rr] = kv ? W[(long)row * K + k] : 0.0f;
                }
                #pragma unroll
                for (int rr = 0; rr < 32; rr++) {
                    int r = rr * 4 + lr;
                    rBs[rr] = kv ? Bsrc[(long)r * ldb + k] : 0.0f;
                }
            }
        }

        // MMA over the staged chunk
        #pragma unroll
        for (int ks = 0; ks < KC; ks += 8) {
            FragA a;
            wmma::load_matrix_sync(a, As + ((warp >> 1) * MJ) * KCP + ks, KCP);
            #pragma unroll
            for (int e = 0; e < a.num_elements; e++) a.x[e] = wmma::__float_to_tf32(a.x[e]);
            #pragma unroll
            for (int s = 0; s < 4; s++) {
                FragB b;
                wmma::load_matrix_sync(b, Bs + ((warp & 1) * 64 + s * 16) * KCP + ks, KCP);
                #pragma unroll
                for (int e = 0; e < b.num_elements; e++) b.x[e] = wmma::__float_to_tf32(b.x[e]);
                wmma::mma_sync(acc[s], a, b, acc[s]);
            }
        }
    }
}

// One "phase" p: CTAs [0,64) run layer-1 step t=p (if p<T);
//                CTAs [64,128) run layer-2 step t=p-1 (if p>=1).
// Kernel boundary between phases is the global barrier.
__global__ __launch_bounds__(256) void phase_kernel(Params P)
{
    extern __shared__ float sm[];      // As(64*KCP) + Bs(128*KCP); front 8192 reused as Cs
    float* As = sm;
    float* Bs = sm + 64 * KCP;

    const int  cta  = blockIdx.x;
    const bool isL2 = (cta >= NJT);
    const int  jt   = cta & (NJT - 1);
    const int  warp = threadIdx.x >> 5;

    FragC acc[4];
    #pragma unroll
    for (int s = 0; s < 4; s++) wmma::fill_fragment(acc[s], 0.0f);

    const float *bihA, *bhhA, *c_in;
    float *c_out, *h_out;

    if (!isL2) {
        if (P.p >= TT) return;
        // gates1 = h1 @ Whh1^T + x_t @ Wih1^T
        gemm_part<true >(P.Whh1, HH, P.h1_in, HH, jt, As, Bs, acc);
        gemm_part<false>(P.Wih1, II, P.x + (long)P.p * II, (long)TT * II, jt, As, Bs, acc);
        bihA = P.bih1; bhhA = P.bhh1;
        c_in = P.c1_in; c_out = P.c1_out; h_out = P.h1_out;
    } else {
        if (P.p < 1) return;
        // gates2 = h1 @ Wih2^T + h2 @ Whh2^T   (h1 = output of layer-1 step p-1)
        gemm_part<true>(P.Wih2, HH, P.h1_in, HH, jt, As, Bs, acc);
        gemm_part<true>(P.Whh2, HH, P.h2_in, HH, jt, As, Bs, acc);
        bihA = P.bih2; bhhA = P.bhh2;
        c_in = P.c2_in; c_out = P.c2_out; h_out = P.h2_out;
    }

    // Dump accumulators to SMEM: Cs[g][j][b], g*2048 + j*128 + b
    __syncthreads();
    #pragma unroll
    for (int s = 0; s < 4; s++)
        wmma::store_matrix_sync(sm + (warp >> 1) * (MJ * 128) + (warp & 1) * 64 + s * 16,
                                acc[s], 128, wmma::mem_row_major);
    __syncthreads();

    // Fused LSTM cell epilogue (PyTorch gate order i,f,g,o)
    const int tid = threadIdx.x;
    #pragma unroll
    for (int it = 0; it < 8; it++) {
        int idx  = it * 256 + tid;     // 0..2047 = (16 j) x (128 b)
        int j    = idx >> 7;
        int b    = idx & 127;
        int hrow = jt * MJ + j;
        float gi = sm[0 * 2048 + j * 128 + b] + bihA[hrow]          + bhhA[hrow];
        float gf = sm[1 * 2048 + j * 128 + b] + bihA[HH + hrow]     + bhhA[HH + hrow];
        float gg = sm[2 * 2048 + j * 128 + b] + bihA[2 * HH + hrow] + bhhA[2 * HH + hrow];
        float go = sm[3 * 2048 + j * 128 + b] + bihA[3 * HH + hrow] + bhhA[3 * HH + hrow];
        float c  = c_in[b * HH + hrow];
        float cn = sigm(gf) * c + sigm(gi) * tanhf(gg);
        float hn = sigm(go) * tanhf(cn);
        c_out[b * HH + hrow] = cn;
        h_out[b * HH + hrow] = hn;
    }
}

// out[b][c] = h2[b] . Wfc[c] + bfc[c]
__global__ void fc_kernel(const float* __restrict__ h2, const float* __restrict__ Wfc,
                          const float* __restrict__ bfc, float* __restrict__ out)
{
    const int c = blockIdx.x;
    const int b = blockIdx.y;
    float s = 0.0f;
    for (int k = threadIdx.x; k < HH; k += 128)
        s += h2[(long)b * HH + k] * Wfc[(long)c * HH + k];
    #pragma unroll
    for (int o = 16; o; o >>= 1) s += __shfl_down_sync(0xffffffffu, s, o);
    __shared__ float ws[4];
    if ((threadIdx.x & 31) == 0) ws[threadIdx.x >> 5] = s;
    __syncthreads();
    if (threadIdx.x == 0)
        out[b * CC + c] = ws[0] + ws[1] + ws[2] + ws[3] + bfc[c];
}

extern "C" void kernel_launch(void* const* d_in, const int* in_sizes, int n_in,
                              void* d_out, int out_size)
{
    const float* x    = (const float*)d_in[0];
    const float* h1   = (const float*)d_in[1];
    const float* c1   = (const float*)d_in[2];
    const float* h2   = (const float*)d_in[3];
    const float* c2   = (const float*)d_in[4];
    const float* Wih1 = (const float*)d_in[5];
    const float* Whh1 = (const float*)d_in[6];
    const float* bih1 = (const float*)d_in[7];
    const float* bhh1 = (const float*)d_in[8];
    const float* Wih2 = (const float*)d_in[9];
    const float* Whh2 = (const float*)d_in[10];
    const float* bih2 = (const float*)d_in[11];
    const float* bhh2 = (const float*)d_in[12];
    const float* Wfc  = (const float*)d_in[13];
    const float* bfc  = (const float*)d_in[14];
    // d_in[15] = mode (0 == 'val'), ignored
    float* out = (float*)d_out;

    // Dynamic SMEM above 48 KB requires an explicit opt-in. Called unconditionally
    // every invocation (idempotent host-side attribute set — not an allocation,
    // no static guards per harness rules).
    cudaFuncSetAttribute(phase_kernel, cudaFuncAttributeMaxDynamicSharedMemorySize, SM_BYTES);

    float* base = nullptr;
    cudaGetSymbolAddress((void**)&base, g_buf);
    const size_t N1 = (size_t)BB * HH;
    float* h1b[2] = { base + 0 * N1, base + 1 * N1 };
    float* c1b[2] = { base + 2 * N1, base + 3 * N1 };
    float* h2b[2] = { base + 4 * N1, base + 5 * N1 };
    float* c2b[2] = { base + 6 * N1, base + 7 * N1 };

    // Initialize phase-0 state from harness inputs (all zeros, but stay generic)
    cudaMemcpyAsync(h1b[0], h1, N1 * sizeof(float), cudaMemcpyDeviceToDevice);
    cudaMemcpyAsync(c1b[0], c1, N1 * sizeof(float), cudaMemcpyDeviceToDevice);
    cudaMemcpyAsync(h2b[0], h2, N1 * sizeof(float), cudaMemcpyDeviceToDevice);
    cudaMemcpyAsync(c2b[0], c2, N1 * sizeof(float), cudaMemcpyDeviceToDevice);

    // Phase p: layer-1 computes step t=p reading h1b[p&1] -> h1b[(p+1)&1];
    //          layer-2 computes step t=p-1 reading the SAME h1b[p&1] (written last phase),
    //          h2/c2 read [(p+1)&1] -> write [p&1].
    for (int p = 0; p <= TT; p++) {
        Params P;
        P.x = x;
        P.Wih1 = Wih1; P.Whh1 = Whh1; P.bih1 = bih1; P.bhh1 = bhh1;
        P.Wih2 = Wih2; P.Whh2 = Whh2; P.bih2 = bih2; P.bhh2 = bhh2;
        P.h1_in = h1b[p & 1];        P.h1_out = h1b[(p + 1) & 1];
        P.c1_in = c1b[p & 1];        P.c1_out = c1b[(p + 1) & 1];
        P.h2_in = h2b[(p + 1) & 1];  P.h2_out = h2b[p & 1];
        P.c2_in = c2b[(p + 1) & 1];  P.c2_out = c2b[p & 1];
        P.p = p;
        phase_kernel<<<2 * NJT, 256, SM_BYTES>>>(P);
    }

    // Final h2 lives in h2b[TT & 1] == h2b[0]
    fc_kernel<<<dim3(CC, BB), 128>>>(h2b[0], Wfc, bfc, out);
}

// round 9
// speedup vs baseline: 1.3437x; 1.3437x over previous
#include <cuda_runtime.h>
#include <mma.h>

using namespace nvcuda;

// Problem constants
#define BB 128       // batch
#define TT 256       // timesteps
#define HH 1024      // hidden
#define II 150       // input features (J*D = 50*3)
#define CC 60        // classes
#define KC 64        // K-chunk staged in SMEM
#define KCP 68       // padded row stride (floats): 272B -> 4-bank row shift vs 8-way conflicts
#define MJ 16        // hidden units per CTA tile
#define BH 64        // batch rows per CTA (batch split in 2)
#define NJT (HH/MJ)  // 64 j-tiles per layer

// Static SMEM: As (64 rows) + Bs (64 rows), each KCP floats wide = 34816 B.
#define SM_FLOATS (64 * KCP + 64 * KCP)

// Ping-pong state buffers: [h1 x2, c1 x2, h2 x2, c2 x2], each B*H floats (4 MB total)
__device__ float g_buf[8][BB * HH];

typedef wmma::fragment<wmma::matrix_a, 16, 16, 8, wmma::precision::tf32, wmma::row_major> FragA;
typedef wmma::fragment<wmma::matrix_b, 16, 16, 8, wmma::precision::tf32, wmma::col_major> FragB;
typedef wmma::fragment<wmma::accumulator, 16, 16, 8, float> FragC;

struct Params {
    const float *x;
    const float *Wih1, *Whh1, *bih1, *bhh1;
    const float *Wih2, *Whh2, *bih2, *bhh2;
    const float *h1_in, *c1_in, *h2_in, *c2_in;
    float *h1_out, *c1_out, *h2_out, *c2_out;
    int p;
};

__device__ __forceinline__ float sigm(float v) { return 1.0f / (1.0f + expf(-v)); }

__device__ __forceinline__ float4 tf32_f4(float4 v) {
    v.x = wmma::__float_to_tf32(v.x);
    v.y = wmma::__float_to_tf32(v.y);
    v.z = wmma::__float_to_tf32(v.z);
    v.w = wmma::__float_to_tf32(v.w);
    return v;
}

// Accumulates acc += W_tile @ B^T over K, for 4 gates x MJ rows x BH batch rows.
// W: [4H, K] row-major, rows used: g*HH + jt*MJ + j  (g in 0..3, j in 0..15)
// Bsrc: BH batch rows (caller pre-offsets by bh*64 rows), row stride ldb.
// AL4 = true requires: K % KC == 0, ldb % 4 == 0, 16B-aligned bases (K=1024 paths).
// Values are pre-truncated to tf32 at staging -> no per-fragment conversion.
// Software-pipelined: next chunk prefetched into registers during current MMA.
template<bool AL4>
__device__ void gemm_part(const float* __restrict__ W, int K,
                          const float* __restrict__ Bsrc, long ldb,
                          int jt, float* As, float* Bs, FragC acc[2])
{
    const int tid  = threadIdx.x;
    const int warp = tid >> 5;

    float4 rA4[4], rB4[4];
    float  rAs[16], rBs[16];

    const int q  = tid & 15;            // AL4: float4 column (0..15)
    const int rs = tid >> 4;            // AL4: staged row offset (0..15)
    const int lr = tid >> 6;            // scalar: row offset (0..3)
    const int kk = tid & 63;            // scalar: column (0..63)

    const float4* W4 = (const float4*)W;
    const float4* B4 = (const float4*)Bsrc;
    const long Kq   = (long)(K >> 2);
    const long ldb4 = ldb >> 2;

    // Prefetch chunk 0
    if (AL4) {
        const long kw4 = q;
        #pragma unroll
        for (int rr = 0; rr < 4; rr++) {
            int r   = rr * 16 + rs;                       // 0..63 A rows
            int row = (r >> 4) * HH + jt * MJ + (r & 15);
            rA4[rr] = W4[(long)row * Kq + kw4];
        }
        #pragma unroll
        for (int rr = 0; rr < 4; rr++) {
            int r = rr * 16 + rs;                         // 0..63 batch rows
            rB4[rr] = B4[(long)r * ldb4 + kw4];
        }
    } else {
        const int  k  = kk;
        const bool kv = (k < K);
        #pragma unroll
        for (int rr = 0; rr < 16; rr++) {
            int r   = rr * 4 + lr;
            int row = (r >> 4) * HH + jt * MJ + (r & 15);
            rAs[rr] = kv ? W[(long)row * K + k] : 0.0f;
        }
        #pragma unroll
        for (int rr = 0; rr < 16; rr++) {
            int r = rr * 4 + lr;
            rBs[rr] = kv ? Bsrc[(long)r * ldb + k] : 0.0f;
        }
    }

    for (int k0 = 0; k0 < K; k0 += KC) {
        __syncthreads();                 // previous chunk's MMA done reading SMEM
        // Commit prefetched registers -> SMEM, truncated to tf32 (idempotent).
        if (AL4) {
            float4* As4 = (float4*)As;
            float4* Bs4 = (float4*)Bs;
            #pragma unroll
            for (int rr = 0; rr < 4; rr++) {
                int r = rr * 16 + rs;
                As4[r * (KCP / 4) + q] = tf32_f4(rA4[rr]);
            }
            #pragma unroll
            for (int rr = 0; rr < 4; rr++) {
                int r = rr * 16 + rs;
                Bs4[r * (KCP / 4) + q] = tf32_f4(rB4[rr]);
            }
        } else {
            #pragma unroll
            for (int rr = 0; rr < 16; rr++) {
                int r = rr * 4 + lr;
                As[r * KCP + kk] = wmma::__float_to_tf32(rAs[rr]);
            }
            #pragma unroll
            for (int rr = 0; rr < 16; rr++) {
                int r = rr * 4 + lr;
                Bs[r * KCP + kk] = wmma::__float_to_tf32(rBs[rr]);
            }
        }
        __syncthreads();                 // chunk visible to all warps

        // Prefetch NEXT chunk into registers — overlaps the MMA below
        const int kn = k0 + KC;
        if (kn < K) {
            if (AL4) {
                const long kw4 = (long)(kn >> 2) + q;
                #pragma unroll
                for (int rr = 0; rr < 4; rr++) {
                    int r   = rr * 16 + rs;
                    int row = (r >> 4) * HH + jt * MJ + (r & 15);
                    rA4[rr] = W4[(long)row * Kq + kw4];
                }
                #pragma unroll
                for (int rr = 0; rr < 4; rr++) {
                    int r = rr * 16 + rs;
                    rB4[rr] = B4[(long)r * ldb4 + kw4];
                }
            } else {
                const int  k  = kn + kk;
                const bool kv = (k < K);
                #pragma unroll
                for (int rr = 0; rr < 16; rr++) {
                    int r   = rr * 4 + lr;
                    int row = (r >> 4) * HH + jt * MJ + (r & 15);
                    rAs[rr] = kv ? W[(long)row * K + k] : 0.0f;
                }
                #pragma unroll
                for (int rr = 0; rr < 16; rr++) {
                    int r = rr * 4 + lr;
                    rBs[rr] = kv ? Bsrc[(long)r * ldb + k] : 0.0f;
                }
            }
        }

        // MMA over the staged chunk.
        // Warp w: gate g = w>>1 (A rows g*16..+16), batch half bh = w&1 (cols bh*32..+32).
        #pragma unroll
        for (int ks = 0; ks < KC; ks += 8) {
            FragA a;
            wmma::load_matrix_sync(a, As + ((warp >> 1) * MJ) * KCP + ks, KCP);
            #pragma unroll
            for (int s = 0; s < 2; s++) {
                FragB b;
                wmma::load_matrix_sync(b, Bs + ((warp & 1) * 32 + s * 16) * KCP + ks, KCP);
                wmma::mma_sync(acc[s], a, b, acc[s]);
            }
        }
    }
}

// One "phase" p: CTAs [0,128) run layer-1 step t=p (if p<T);
//                CTAs [128,256) run layer-2 step t=p-1 (if p>=1).
// Within a layer: jt = (cta>>1) & 63 selects 16 hidden units, bh = cta&1 the batch half.
// Kernel boundary between phases is the global barrier.
__global__ __launch_bounds__(256, 2) void phase_kernel(Params P)
{
    __shared__ float sm[SM_FLOATS];    // As(64*KCP) + Bs(64*KCP); front 4096 reused as Cs
    float* As = sm;
    float* Bs = sm + 64 * KCP;

    const int  cta  = blockIdx.x;
    const bool isL2 = (cta >= 2 * NJT);
    const int  sub  = cta & (2 * NJT - 1);
    const int  jt   = sub >> 1;
    const int  bh   = sub & 1;
    const int  warp = threadIdx.x >> 5;
    const long boff = (long)bh * BH;    // batch-row offset

    FragC acc[2];
    #pragma unroll
    for (int s = 0; s < 2; s++) wmma::fill_fragment(acc[s], 0.0f);

    const float *bihA, *bhhA, *c_in;
    float *c_out, *h_out;

    if (!isL2) {
        if (P.p >= TT) return;
        // gates1 = h1 @ Whh1^T + x_t @ Wih1^T
        gemm_part<true >(P.Whh1, HH, P.h1_in + boff * HH, HH, jt, As, Bs, acc);
        gemm_part<false>(P.Wih1, II, P.x + (long)P.p * II + boff * TT * II, (long)TT * II,
                         jt, As, Bs, acc);
        bihA = P.bih1; bhhA = P.bhh1;
        c_in = P.c1_in; c_out = P.c1_out; h_out = P.h1_out;
    } else {
        if (P.p < 1) return;
        // gates2 = h1 @ Wih2^T + h2 @ Whh2^T   (h1 = output of layer-1 step p-1)
        gemm_part<true>(P.Wih2, HH, P.h1_in + boff * HH, HH, jt, As, Bs, acc);
        gemm_part<true>(P.Whh2, HH, P.h2_in + boff * HH, HH, jt, As, Bs, acc);
        bihA = P.bih2; bhhA = P.bhh2;
        c_in = P.c2_in; c_out = P.c2_out; h_out = P.h2_out;
    }

    // Dump accumulators to SMEM: Cs[row=g*16+j][col=bl], ldm 64 (4096 floats, fits in As)
    __syncthreads();
    #pragma unroll
    for (int s = 0; s < 2; s++)
        wmma::store_matrix_sync(sm + ((warp >> 1) * MJ) * BH + (warp & 1) * 32 + s * 16,
                                acc[s], BH, wmma::mem_row_major);
    __syncthreads();

    // Fused LSTM cell epilogue (PyTorch gate order i,f,g,o): 16 j x 64 bl outputs.
    const int tid = threadIdx.x;
    #pragma unroll
    for (int it = 0; it < 4; it++) {
        int idx  = it * 256 + tid;     // 0..1023
        int j    = idx >> 6;
        int bl   = idx & 63;
        int b    = bh * BH + bl;
        int hrow = jt * MJ + j;
        float gi = sm[(0 * MJ + j) * BH + bl] + bihA[hrow]          + bhhA[hrow];
        float gf = sm[(1 * MJ + j) * BH + bl] + bihA[HH + hrow]     + bhhA[HH + hrow];
        float gg = sm[(2 * MJ + j) * BH + bl] + bihA[2 * HH + hrow] + bhhA[2 * HH + hrow];
        float go = sm[(3 * MJ + j) * BH + bl] + bihA[3 * HH + hrow] + bhhA[3 * HH + hrow];
        float c  = c_in[(long)b * HH + hrow];
        float cn = sigm(gf) * c + sigm(gi) * tanhf(gg);
        float hn = sigm(go) * tanhf(cn);
        c_out[(long)b * HH + hrow] = cn;
        h_out[(long)b * HH + hrow] = hn;
    }
}

// out[b][c] = h2[b] . Wfc[c] + bfc[c]
__global__ void fc_kernel(const float* __restrict__ h2, const float* __restrict__ Wfc,
                          const float* __restrict__ bfc, float* __restrict__ out)
{
    const int c = blockIdx.x;
    const int b = blockIdx.y;
    float s = 0.0f;
    for (int k = threadIdx.x; k < HH; k += 128)
        s += h2[(long)b * HH + k] * Wfc[(long)c * HH + k];
    #pragma unroll
    for (int o = 16; o; o >>= 1) s += __shfl_down_sync(0xffffffffu, s, o);
    __shared__ float ws[4];
    if ((threadIdx.x & 31) == 0) ws[threadIdx.x >> 5] = s;
    __syncthreads();
    if (threadIdx.x == 0)
        out[b * CC + c] = ws[0] + ws[1] + ws[2] + ws[3] + bfc[c];
}

extern "C" void kernel_launch(void* const* d_in, const int* in_sizes, int n_in,
                              void* d_out, int out_size)
{
    const float* x    = (const float*)d_in[0];
    const float* h1   = (const float*)d_in[1];
    const float* c1   = (const float*)d_in[2];
    const float* h2   = (const float*)d_in[3];
    const float* c2   = (const float*)d_in[4];
    const float* Wih1 = (const float*)d_in[5];
    const float* Whh1 = (const float*)d_in[6];
    const float* bih1 = (const float*)d_in[7];
    const float* bhh1 = (const float*)d_in[8];
    const float* Wih2 = (const float*)d_in[9];
    const float* Whh2 = (const float*)d_in[10];
    const float* bih2 = (const float*)d_in[11];
    const float* bhh2 = (const float*)d_in[12];
    const float* Wfc  = (const float*)d_in[13];
    const float* bfc  = (const float*)d_in[14];
    // d_in[15] = mode (0 == 'val'), ignored
    float* out = (float*)d_out;

    float* base = nullptr;
    cudaGetSymbolAddress((void**)&base, g_buf);
    const size_t N1 = (size_t)BB * HH;
    float* h1b[2] = { base + 0 * N1, base + 1 * N1 };
    float* c1b[2] = { base + 2 * N1, base + 3 * N1 };
    float* h2b[2] = { base + 4 * N1, base + 5 * N1 };
    float* c2b[2] = { base + 6 * N1, base + 7 * N1 };

    // Initialize phase-0 state from harness inputs (all zeros, but stay generic)
    cudaMemcpyAsync(h1b[0], h1, N1 * sizeof(float), cudaMemcpyDeviceToDevice);
    cudaMemcpyAsync(c1b[0], c1, N1 * sizeof(float), cudaMemcpyDeviceToDevice);
    cudaMemcpyAsync(h2b[0], h2, N1 * sizeof(float), cudaMemcpyDeviceToDevice);
    cudaMemcpyAsync(c2b[0], c2, N1 * sizeof(float), cudaMemcpyDeviceToDevice);

    // Phase p: layer-1 computes step t=p reading h1b[p&1] -> h1b[(p+1)&1];
    //          layer-2 computes step t=p-1 reading the SAME h1b[p&1] (written last phase),
    //          h2/c2 read [(p+1)&1] -> write [p&1].
    for (int p = 0; p <= TT; p++) {
        Params P;
        P.x = x;
        P.Wih1 = Wih1; P.Whh1 = Whh1; P.bih1 = bih1; P.bhh1 = bhh1;
        P.Wih2 = Wih2; P.Whh2 = Whh2; P.bih2 = bih2; P.bhh2 = bhh2;
        P.h1_in = h1b[p & 1];        P.h1_out = h1b[(p + 1) & 1];
        P.c1_in = c1b[p & 1];        P.c1_out = c1b[(p + 1) & 1];
        P.h2_in = h2b[(p + 1) & 1];  P.h2_out = h2b[p & 1];
        P.c2_in = c2b[(p + 1) & 1];  P.c2_out = c2b[p & 1];
        P.p = p;
        phase_kernel<<<4 * NJT, 256>>>(P);
    }

    // Final h2 lives in h2b[TT & 1] == h2b[0]
    fc_kernel<<<dim3(CC, BB), 128>>>(h2b[0], Wfc, bfc, out);
}

// round 11
// speedup vs baseline: 1.4204x; 1.0571x over previous
#include <cuda_runtime.h>
#include <mma.h>

using namespace nvcuda;

// Problem constants
#define BB 128       // batch
#define TT 256       // timesteps
#define HH 1024      // hidden
#define II 150       // input features (J*D = 50*3)
#define CC 60        // classes
#define KC 64        // K-chunk staged in SMEM
#define KCP 68       // padded row stride (floats): 272B row shift kills 8-way bank conflicts
#define MJ 16        // hidden units per CTA tile
#define NJT (HH/MJ)  // 64 j-tiles per layer

#define NTHREADS 512
#define BUFS (192 * KCP)          // one stage: As (64 rows) + Bs (128 rows), KCP floats each
#define SM_FLOATS (2 * BUFS)      // two stages (double buffer); Cs (8192 fl) aliases stage 0
#define SM_BYTES (SM_FLOATS * 4)  // 104448 B

// Ping-pong state buffers: [h1 x2, c1 x2, h2 x2, c2 x2], each B*H floats (4 MB total)
__device__ float g_buf[8][BB * HH];

typedef wmma::fragment<wmma::matrix_a, 16, 16, 8, wmma::precision::tf32, wmma::row_major> FragA;
typedef wmma::fragment<wmma::matrix_b, 16, 16, 8, wmma::precision::tf32, wmma::col_major> FragB;
typedef wmma::fragment<wmma::accumulator, 16, 16, 8, float> FragC;

struct Params {
    const float *x;
    const float *Wih1, *Whh1, *bih1, *bhh1;
    const float *Wih2, *Whh2, *bih2, *bhh2;
    const float *h1_in, *c1_in, *h2_in, *c2_in;
    float *h1_out, *c1_out, *h2_out, *c2_out;
    int p;
};

__device__ __forceinline__ float sigm(float v) { return 1.0f / (1.0f + expf(-v)); }

__device__ __forceinline__ float4 tf32_f4(float4 v) {
    v.x = wmma::__float_to_tf32(v.x);
    v.y = wmma::__float_to_tf32(v.y);
    v.z = wmma::__float_to_tf32(v.z);
    v.w = wmma::__float_to_tf32(v.w);
    return v;
}

// Accumulates acc += W_tile @ B^T over K: 4 gates x MJ rows (M=64) x full batch (N=128).
// W: [4H, K] row-major, rows used: g*HH + jt*MJ + j.  Bsrc: 128 batch rows, stride ldb.
// AL4: K % KC == 0, 16B-aligned, ldb % 4 == 0.  Values tf32-truncated at staging.
// 2-stage double buffer, ONE barrier per chunk:
//   window c:  STS(chunk c -> buf[c&1]) ; LDG(chunk c+1 -> regs) ; barrier ; MMA(buf[c&1])
// __syncthreads() fences prior SMEM reads, so overwriting buf[(c+1)&1] (last read in
// window c-1, pre-barrier-c) is safe. Across parts: all AL4 parts have nc=16 (even), so
// the next part's first STS (buf0) never collides with the last MMA's buffer (buf1);
// the nc=3 scalar part is final and is followed by the epilogue barrier.
template<bool AL4>
__device__ void gemm_part(const float* __restrict__ W, int K,
                          const float* __restrict__ Bsrc, long ldb,
                          int jt, float* smbase, FragC acc[2])
{
    const int tid  = threadIdx.x;
    const int warp = tid >> 5;
    const int g    = warp >> 2;       // gate 0..3
    const int bq   = warp & 3;        // batch quarter 0..3 (N=32 each)

    float4 rA4[2], rB4[4];
    float  rAs[8], rBs[16];

    const int q  = tid & 15;          // AL4: float4 column (0..15)
    const int rs = tid >> 4;          // AL4: staged row (0..31)
    const int lr = tid >> 6;          // scalar: row offset (0..7)
    const int kk = tid & 63;          // scalar: column (0..63)

    const float4* W4 = (const float4*)W;
    const float4* B4 = (const float4*)Bsrc;
    const long Kq   = (long)(K >> 2);
    const long ldb4 = ldb >> 2;
    const int  nc   = (K + KC - 1) / KC;

    // Prologue: prefetch chunk 0 into registers
    if (AL4) {
        const long kw4 = q;
        #pragma unroll
        for (int rr = 0; rr < 2; rr++) {
            int r   = rr * 32 + rs;                        // 0..63 A rows
            int row = (r >> 4) * HH + jt * MJ + (r & 15);
            rA4[rr] = W4[(long)row * Kq + kw4];
        }
        #pragma unroll
        for (int rr = 0; rr < 4; rr++) {
            int r = rr * 32 + rs;                          // 0..127 batch rows
            rB4[rr] = B4[(long)r * ldb4 + kw4];
        }
    } else {
        const bool kv = (kk < K);
        #pragma unroll
        for (int rr = 0; rr < 8; rr++) {
            int r   = rr * 8 + lr;
            int row = (r >> 4) * HH + jt * MJ + (r & 15);
            rAs[rr] = kv ? W[(long)row * K + kk] : 0.0f;
        }
        #pragma unroll
        for (int rr = 0; rr < 16; rr++) {
            int r = rr * 8 + lr;
            rBs[rr] = kv ? Bsrc[(long)r * ldb + kk] : 0.0f;
        }
    }

    for (int c = 0; c < nc; c++) {
        float* As = smbase + (c & 1) * BUFS;
        float* Bs = As + 64 * KCP;

        // Commit prefetched chunk c to SMEM (tf32-truncated; idempotent).
        if (AL4) {
            float4* As4 = (float4*)As;
            float4* Bs4 = (float4*)Bs;
            #pragma unroll
            for (int rr = 0; rr < 2; rr++) {
                int r = rr * 32 + rs;
                As4[r * (KCP / 4) + q] = tf32_f4(rA4[rr]);
            }
            #pragma unroll
            for (int rr = 0; rr < 4; rr++) {
                int r = rr * 32 + rs;
                Bs4[r * (KCP / 4) + q] = tf32_f4(rB4[rr]);
            }
        } else {
            #pragma unroll
            for (int rr = 0; rr < 8; rr++) {
                int r = rr * 8 + lr;
                As[r * KCP + kk] = wmma::__float_to_tf32(rAs[rr]);
            }
            #pragma unroll
            for (int rr = 0; rr < 16; rr++) {
                int r = rr * 8 + lr;
                Bs[r * KCP + kk] = wmma::__float_to_tf32(rBs[rr]);
            }
        }

        // Prefetch chunk c+1 — latency spans the barrier AND the MMA below.
        const int kn = (c + 1) * KC;
        if (c + 1 < nc) {
            if (AL4) {
                const long kw4 = (long)(kn >> 2) + q;
                #pragma unroll
                for (int rr = 0; rr < 2; rr++) {
                    int r   = rr * 32 + rs;
                    int row = (r >> 4) * HH + jt * MJ + (r & 15);
                    rA4[rr] = W4[(long)row * Kq + kw4];
                }
                #pragma unroll
                for (int rr = 0; rr < 4; rr++) {
                    int r = rr * 32 + rs;
                    rB4[rr] = B4[(long)r * ldb4 + kw4];
                }
            } else {
                const int  k  = kn + kk;
                const bool kv = (k < K);
                #pragma unroll
                for (int rr = 0; rr < 8; rr++) {
                    int r   = rr * 8 + lr;
                    int row = (r >> 4) * HH + jt * MJ + (r & 15);
                    rAs[rr] = kv ? W[(long)row * K + k] : 0.0f;
                }
                #pragma unroll
                for (int rr = 0; rr < 16; rr++) {
                    int r = rr * 8 + lr;
                    rBs[rr] = kv ? Bsrc[(long)r * ldb + k] : 0.0f;
                }
            }
        }

        __syncthreads();

        // MMA over staged chunk c. Warp: A rows g*16..+16, B rows bq*32..+32.
        #pragma unroll
        for (int ks = 0; ks < KC; ks += 8) {
            FragA a;
            wmma::load_matrix_sync(a, As + (g * MJ) * KCP + ks, KCP);
            FragB b0;
            wmma::load_matrix_sync(b0, Bs + (bq * 32) * KCP + ks, KCP);
            wmma::mma_sync(acc[0], a, b0, acc[0]);
            FragB b1;
            wmma::load_matrix_sync(b1, Bs + (bq * 32 + 16) * KCP + ks, KCP);
            wmma::mma_sync(acc[1], a, b1, acc[1]);
        }
    }
}

// One "phase" p: CTAs [0,64) run layer-1 step t=p (if p<T);
//                CTAs [64,128) run layer-2 step t=p-1 (if p>=1).
// Kernel boundary between phases is the global barrier.
__global__ __launch_bounds__(NTHREADS, 1) void phase_kernel(Params P)
{
    extern __shared__ float sm[];      // 2 stages; Cs (64x128) aliases stage 0

    const int  cta  = blockIdx.x;
    const bool isL2 = (cta >= NJT);
    const int  jt   = cta & (NJT - 1);
    const int  warp = threadIdx.x >> 5;
    const int  g    = warp >> 2;
    const int  bq   = warp & 3;

    FragC acc[2];
    wmma::fill_fragment(acc[0], 0.0f);
    wmma::fill_fragment(acc[1], 0.0f);

    const float *bihA, *bhhA, *c_in;
    float *c_out, *h_out;

    if (!isL2) {
        if (P.p >= TT) return;
        // gates1 = h1 @ Whh1^T + x_t @ Wih1^T
        gemm_part<true >(P.Whh1, HH, P.h1_in, HH, jt, sm, acc);
        gemm_part<false>(P.Wih1, II, P.x + (long)P.p * II, (long)TT * II, jt, sm, acc);
        bihA = P.bih1; bhhA = P.bhh1;
        c_in = P.c1_in; c_out = P.c1_out; h_out = P.h1_out;
    } else {
        if (P.p < 1) return;
        // gates2 = h1 @ Wih2^T + h2 @ Whh2^T   (h1 = output of layer-1 step p-1)
        gemm_part<true>(P.Wih2, HH, P.h1_in, HH, jt, sm, acc);
        gemm_part<true>(P.Whh2, HH, P.h2_in, HH, jt, sm, acc);
        bihA = P.bih2; bhhA = P.bhh2;
        c_in = P.c2_in; c_out = P.c2_out; h_out = P.h2_out;
    }

    // Dump accumulators to SMEM: Cs[row = g*16+j][col = b], ldm 128 (8192 floats)
    __syncthreads();
    wmma::store_matrix_sync(sm + (g * MJ) * BB + bq * 32,      acc[0], BB, wmma::mem_row_major);
    wmma::store_matrix_sync(sm + (g * MJ) * BB + bq * 32 + 16, acc[1], BB, wmma::mem_row_major);
    __syncthreads();

    // Fused LSTM cell epilogue (PyTorch gate order i,f,g,o): 16 j x 128 b outputs.
    const int tid = threadIdx.x;
    #pragma unroll
    for (int it = 0; it < 4; it++) {
        int idx  = it * NTHREADS + tid;  // 0..2047
        int j    = idx >> 7;             // 0..15
        int b    = idx & 127;
        int hrow = jt * MJ + j;
        float gi = sm[(0 * MJ + j) * BB + b] + bihA[hrow]          + bhhA[hrow];
        float gf = sm[(1 * MJ + j) * BB + b] + bihA[HH + hrow]     + bhhA[HH + hrow];
        float gg = sm[(2 * MJ + j) * BB + b] + bihA[2 * HH + hrow] + bhhA[2 * HH + hrow];
        float go = sm[(3 * MJ + j) * BB + b] + bihA[3 * HH + hrow] + bhhA[3 * HH + hrow];
        float c  = c_in[(long)b * HH + hrow];
        float cn = sigm(gf) * c + sigm(gi) * tanhf(gg);
        float hn = sigm(go) * tanhf(cn);
        c_out[(long)b * HH + hrow] = cn;
        h_out[(long)b * HH + hrow] = hn;
    }
}

// out[b][c] = h2[b] . Wfc[c] + bfc[c]
__global__ void fc_kernel(const float* __restrict__ h2, const float* __restrict__ Wfc,
                          const float* __restrict__ bfc, float* __restrict__ out)
{
    const int c = blockIdx.x;
    const int b = blockIdx.y;
    float s = 0.0f;
    for (int k = threadIdx.x; k < HH; k += 128)
        s += h2[(long)b * HH + k] * Wfc[(long)c * HH + k];
    #pragma unroll
    for (int o = 16; o; o >>= 1) s += __shfl_down_sync(0xffffffffu, s, o);
    __shared__ float ws[4];
    if ((threadIdx.x & 31) == 0) ws[threadIdx.x >> 5] = s;
    __syncthreads();
    if (threadIdx.x == 0)
        out[b * CC + c] = ws[0] + ws[1] + ws[2] + ws[3] + bfc[c];
}

extern "C" void kernel_launch(void* const* d_in, const int* in_sizes, int n_in,
                              void* d_out, int out_size)
{
    const float* x    = (const float*)d_in[0];
    const float* h1   = (const float*)d_in[1];
    const float* c1   = (const float*)d_in[2];
    const float* h2   = (const float*)d_in[3];
    const float* c2   = (const float*)d_in[4];
    const float* Wih1 = (const float*)d_in[5];
    const float* Whh1 = (const float*)d_in[6];
    const float* bih1 = (const float*)d_in[7];
    const float* bhh1 = (const float*)d_in[8];
    const float* Wih2 = (const float*)d_in[9];
    const float* Whh2 = (const float*)d_in[10];
    const float* bih2 = (const float*)d_in[11];
    const float* bhh2 = (const float*)d_in[12];
    const float* Wfc  = (const float*)d_in[13];
    const float* bfc  = (const float*)d_in[14];
    // d_in[15] = mode (0 == 'val'), ignored
    float* out = (float*)d_out;

    // Dynamic SMEM > 48 KB opt-in (idempotent host-side attribute; not an allocation).
    cudaFuncSetAttribute(phase_kernel, cudaFuncAttributeMaxDynamicSharedMemorySize, SM_BYTES);

    float* base = nullptr;
    cudaGetSymbolAddress((void**)&base, g_buf);
    const size_t N1 = (size_t)BB * HH;
    float* h1b[2] = { base + 0 * N1, base + 1 * N1 };
    float* c1b[2] = { base + 2 * N1, base + 3 * N1 };
    float* h2b[2] = { base + 4 * N1, base + 5 * N1 };
    float* c2b[2] = { base + 6 * N1, base + 7 * N1 };

    // Initialize phase-0 state from harness inputs (all zeros, but stay generic)
    cudaMemcpyAsync(h1b[0], h1, N1 * sizeof(float), cudaMemcpyDeviceToDevice);
    cudaMemcpyAsync(c1b[0], c1, N1 * sizeof(float), cudaMemcpyDeviceToDevice);
    cudaMemcpyAsync(h2b[0], h2, N1 * sizeof(float), cudaMemcpyDeviceToDevice);
    cudaMemcpyAsync(c2b[0], c2, N1 * sizeof(float), cudaMemcpyDeviceToDevice);

    // Phase p: layer-1 computes step t=p reading h1b[p&1] -> h1b[(p+1)&1];
    //          layer-2 computes step t=p-1 reading the SAME h1b[p&1] (written last phase),
    //          h2/c2 read [(p+1)&1] -> write [p&1].
    for (int p = 0; p <= TT; p++) {
        Params P;
        P.x = x;
        P.Wih1 = Wih1; P.Whh1 = Whh1; P.bih1 = bih1; P.bhh1 = bhh1;
        P.Wih2 = Wih2; P.Whh2 = Whh2; P.bih2 = bih2; P.bhh2 = bhh2;
        P.h1_in = h1b[p & 1];        P.h1_out = h1b[(p + 1) & 1];
        P.c1_in = c1b[p & 1];        P.c1_out = c1b[(p + 1) & 1];
        P.h2_in = h2b[(p + 1) & 1];  P.h2_out = h2b[p & 1];
        P.c2_in = c2b[(p + 1) & 1];  P.c2_out = c2b[p & 1];
        P.p = p;
        phase_kernel<<<2 * NJT, NTHREADS, SM_BYTES>>>(P);
    }

    // Final h2 lives in h2b[TT & 1] == h2b[0]
    fc_kernel<<<dim3(CC, BB), 128>>>(h2b[0], Wfc, bfc, out);
}